// round 2
// baseline (speedup 1.0000x reference)
#include <cuda_runtime.h>

#define B_DIM 8
#define CIN 512
#define COUT 3
#define WDIM 512
#define HW 65536           // 256*256
#define CONV_CLAMP 256.0f

// Precomputed per-(batch, out-channel, in-channel) coefficient:
//   m[b][o][c] = weight[o][c] * styles[b][c]
__device__ float g_m[B_DIM * COUT * CIN];

// ---------------------------------------------------------------------------
// Kernel 1: styles + coefficient precompute.
// One warp computes one (b, c): dot(w[b,:], affine_w[c,:]) with coalesced
// loads over the WDIM axis, warp shfl-reduce, then writes 3 coefficients.
// grid = (CIN / warps_per_block, B), block = 256 (8 warps)
// ---------------------------------------------------------------------------
__global__ void styles_kernel(const float* __restrict__ w,
                              const float* __restrict__ weight,
                              const float* __restrict__ affine_w,
                              const float* __restrict__ affine_b)
{
    __shared__ float w_s[WDIM];
    const int b   = blockIdx.y;
    const int tid = threadIdx.x;

    for (int k = tid; k < WDIM; k += blockDim.x)
        w_s[k] = w[b * WDIM + k];
    __syncthreads();

    const int warp = tid >> 5;
    const int lane = tid & 31;
    const int c = blockIdx.x * (blockDim.x >> 5) + warp;
    if (c >= CIN) return;

    const float* __restrict__ arow = affine_w + (size_t)c * WDIM;
    float sum = 0.0f;
#pragma unroll
    for (int j = 0; j < WDIM / 32; ++j) {
        const int k = lane + 32 * j;
        sum = fmaf(arow[k], w_s[k], sum);
    }
#pragma unroll
    for (int off = 16; off > 0; off >>= 1)
        sum += __shfl_xor_sync(0xffffffffu, sum, off);

    if (lane == 0) {
        const float affine_gain = 1.0f / sqrtf((float)WDIM);
        const float cin_gain    = 1.0f / sqrtf((float)CIN);
        const float style = (sum * affine_gain + affine_b[c]) * cin_gain;
#pragma unroll
        for (int o = 0; o < COUT; ++o)
            g_m[(b * COUT + o) * CIN + c] = weight[o * CIN + c] * style;
    }
}

// ---------------------------------------------------------------------------
// Kernel 2: the streaming reduction.
//   out[b][o][hw] = clamp( sum_c m[b][o][c] * x[b][c][hw] + bias[o] )
// 128-thread blocks (4 warps) for fine-grained wave balance:
// grid = (HW/4/128 = 128, B) = 1024 blocks -> 6.92 blocks/SM, single wave,
// near-zero tail imbalance (vs 3.46/SM with 256-thread blocks, 16% tail).
// Each thread owns one float4 column; c-loop streams x exactly once.
// ---------------------------------------------------------------------------
__global__ void __launch_bounds__(128)
torgb_kernel(const float* __restrict__ x,
             const float* __restrict__ bias,
             float* __restrict__ out)
{
    __shared__ float m0[CIN];
    __shared__ float m1[CIN];
    __shared__ float m2[CIN];

    const int b   = blockIdx.y;
    const int tid = threadIdx.x;

    for (int c = tid; c < CIN; c += blockDim.x) {
        m0[c] = g_m[(b * COUT + 0) * CIN + c];
        m1[c] = g_m[(b * COUT + 1) * CIN + c];
        m2[c] = g_m[(b * COUT + 2) * CIN + c];
    }
    __syncthreads();

    const int hw4 = blockIdx.x * blockDim.x + tid;   // index in float4 units
    const float4* __restrict__ x4 =
        (const float4*)(x + (size_t)b * CIN * HW);

    float4 a0 = make_float4(0.f, 0.f, 0.f, 0.f);
    float4 a1 = make_float4(0.f, 0.f, 0.f, 0.f);
    float4 a2 = make_float4(0.f, 0.f, 0.f, 0.f);

#pragma unroll 8
    for (int c = 0; c < CIN; ++c) {
        const float4 xv = __ldg(&x4[(size_t)c * (HW / 4) + hw4]);
        const float c0 = m0[c];
        const float c1 = m1[c];
        const float c2 = m2[c];
        a0.x = fmaf(xv.x, c0, a0.x); a0.y = fmaf(xv.y, c0, a0.y);
        a0.z = fmaf(xv.z, c0, a0.z); a0.w = fmaf(xv.w, c0, a0.w);
        a1.x = fmaf(xv.x, c1, a1.x); a1.y = fmaf(xv.y, c1, a1.y);
        a1.z = fmaf(xv.z, c1, a1.z); a1.w = fmaf(xv.w, c1, a1.w);
        a2.x = fmaf(xv.x, c2, a2.x); a2.y = fmaf(xv.y, c2, a2.y);
        a2.z = fmaf(xv.z, c2, a2.z); a2.w = fmaf(xv.w, c2, a2.w);
    }

    const float bv0 = bias[0];
    const float bv1 = bias[1];
    const float bv2 = bias[2];

#define CLAMP1(v) fminf(fmaxf((v), -CONV_CLAMP), CONV_CLAMP)
    float4 o0 = make_float4(CLAMP1(a0.x + bv0), CLAMP1(a0.y + bv0),
                            CLAMP1(a0.z + bv0), CLAMP1(a0.w + bv0));
    float4 o1 = make_float4(CLAMP1(a1.x + bv1), CLAMP1(a1.y + bv1),
                            CLAMP1(a1.z + bv1), CLAMP1(a1.w + bv1));
    float4 o2 = make_float4(CLAMP1(a2.x + bv2), CLAMP1(a2.y + bv2),
                            CLAMP1(a2.z + bv2), CLAMP1(a2.w + bv2));
#undef CLAMP1

    float4* __restrict__ out4 = (float4*)out;
    const size_t obase = (size_t)b * COUT * (HW / 4);
    out4[obase + 0 * (HW / 4) + hw4] = o0;
    out4[obase + 1 * (HW / 4) + hw4] = o1;
    out4[obase + 2 * (HW / 4) + hw4] = o2;
}

// ---------------------------------------------------------------------------
// Launch
//   d_in[0] = x        [B, CIN, H, W]  f32
//   d_in[1] = w        [B, WDIM]       f32
//   d_in[2] = weight   [COUT, CIN,1,1] f32
//   d_in[3] = bias     [COUT]          f32
//   d_in[4] = affine_w [CIN, WDIM]     f32
//   d_in[5] = affine_b [CIN]           f32
// ---------------------------------------------------------------------------
extern "C" void kernel_launch(void* const* d_in, const int* in_sizes, int n_in,
                              void* d_out, int out_size)
{
    const float* x        = (const float*)d_in[0];
    const float* w        = (const float*)d_in[1];
    const float* weight   = (const float*)d_in[2];
    const float* bias     = (const float*)d_in[3];
    const float* affine_w = (const float*)d_in[4];
    const float* affine_b = (const float*)d_in[5];
    float* out = (float*)d_out;

    dim3 sgrid(CIN / 8, B_DIM);
    styles_kernel<<<sgrid, 256>>>(w, weight, affine_w, affine_b);

    dim3 cgrid(HW / 4 / 128, B_DIM);
    torgb_kernel<<<cgrid, 128>>>(x, bias, out);
}

// round 3
// speedup vs baseline: 1.1428x; 1.1428x over previous
#include <cuda_runtime.h>

#define B_DIM 8
#define CIN 512
#define COUT 3
#define WDIM 512
#define HW 65536           // 256*256
#define CONV_CLAMP 256.0f

// Precomputed per-(batch, out-channel, in-channel) coefficient:
//   m[b][o][c] = weight[o][c] * styles[b][c]
// Stored [b][c][o]-interleaved as float4 (o0,o1,o2,pad) for one-LDS128 fills.
__device__ float4 g_m4[B_DIM * CIN];

// ---------------------------------------------------------------------------
// Kernel 1: styles + coefficient precompute.
// One warp computes one (b, c): dot(w[b,:], affine_w[c,:]) with coalesced
// loads over the WDIM axis, warp shfl-reduce, then writes 3 coefficients.
// grid = (CIN / 8, B), block = 256 (8 warps)
// ---------------------------------------------------------------------------
__global__ void styles_kernel(const float* __restrict__ w,
                              const float* __restrict__ weight,
                              const float* __restrict__ affine_w,
                              const float* __restrict__ affine_b)
{
    __shared__ float w_s[WDIM];
    const int b   = blockIdx.y;
    const int tid = threadIdx.x;

    for (int k = tid; k < WDIM; k += blockDim.x)
        w_s[k] = w[b * WDIM + k];
    __syncthreads();

    const int warp = tid >> 5;
    const int lane = tid & 31;
    const int c = blockIdx.x * (blockDim.x >> 5) + warp;
    if (c >= CIN) return;

    const float* __restrict__ arow = affine_w + (size_t)c * WDIM;
    float sum = 0.0f;
#pragma unroll
    for (int j = 0; j < WDIM / 32; ++j) {
        const int k = lane + 32 * j;
        sum = fmaf(arow[k], w_s[k], sum);
    }
#pragma unroll
    for (int off = 16; off > 0; off >>= 1)
        sum += __shfl_xor_sync(0xffffffffu, sum, off);

    if (lane == 0) {
        const float affine_gain = 1.0f / sqrtf((float)WDIM);
        const float cin_gain    = 1.0f / sqrtf((float)CIN);
        const float style = (sum * affine_gain + affine_b[c]) * cin_gain;
        float4 m;
        m.x = weight[0 * CIN + c] * style;
        m.y = weight[1 * CIN + c] * style;
        m.z = weight[2 * CIN + c] * style;
        m.w = 0.0f;
        g_m4[b * CIN + c] = m;
    }
}

// ---------------------------------------------------------------------------
// Kernel 2: the streaming reduction.
//   out[b][o][hw] = clamp( sum_c m[b][o][c] * x[b][c][hw] + bias[o] )
// R1 geometry (known-good for the L1tex-queue model: oe*MLP_p1 ~= 14 < 16):
// grid = (64, 8) = 512 blocks x 256 threads, unroll 4.
// x is single-use -> __ldcs evict-first streaming loads; __stcs stores.
// ---------------------------------------------------------------------------
__global__ void __launch_bounds__(256)
torgb_kernel(const float* __restrict__ x,
             const float* __restrict__ bias,
             float* __restrict__ out)
{
    __shared__ float m0[CIN];
    __shared__ float m1[CIN];
    __shared__ float m2[CIN];

    const int b   = blockIdx.y;
    const int tid = threadIdx.x;

    // vectorized coefficient fill: 512 float4 per block, 2 per thread
    for (int c = tid; c < CIN; c += blockDim.x) {
        const float4 m = g_m4[b * CIN + c];
        m0[c] = m.x;
        m1[c] = m.y;
        m2[c] = m.z;
    }
    __syncthreads();

    const int hw4 = blockIdx.x * blockDim.x + tid;   // index in float4 units
    const float4* __restrict__ x4 =
        (const float4*)(x + (size_t)b * CIN * HW);

    float4 a0 = make_float4(0.f, 0.f, 0.f, 0.f);
    float4 a1 = make_float4(0.f, 0.f, 0.f, 0.f);
    float4 a2 = make_float4(0.f, 0.f, 0.f, 0.f);

#pragma unroll 4
    for (int c = 0; c < CIN; ++c) {
        const float4 xv = __ldcs(&x4[(size_t)c * (HW / 4) + hw4]);
        const float c0 = m0[c];
        const float c1 = m1[c];
        const float c2 = m2[c];
        a0.x = fmaf(xv.x, c0, a0.x); a0.y = fmaf(xv.y, c0, a0.y);
        a0.z = fmaf(xv.z, c0, a0.z); a0.w = fmaf(xv.w, c0, a0.w);
        a1.x = fmaf(xv.x, c1, a1.x); a1.y = fmaf(xv.y, c1, a1.y);
        a1.z = fmaf(xv.z, c1, a1.z); a1.w = fmaf(xv.w, c1, a1.w);
        a2.x = fmaf(xv.x, c2, a2.x); a2.y = fmaf(xv.y, c2, a2.y);
        a2.z = fmaf(xv.z, c2, a2.z); a2.w = fmaf(xv.w, c2, a2.w);
    }

    const float bv0 = bias[0];
    const float bv1 = bias[1];
    const float bv2 = bias[2];

#define CLAMP1(v) fminf(fmaxf((v), -CONV_CLAMP), CONV_CLAMP)
    float4 o0 = make_float4(CLAMP1(a0.x + bv0), CLAMP1(a0.y + bv0),
                            CLAMP1(a0.z + bv0), CLAMP1(a0.w + bv0));
    float4 o1 = make_float4(CLAMP1(a1.x + bv1), CLAMP1(a1.y + bv1),
                            CLAMP1(a1.z + bv1), CLAMP1(a1.w + bv1));
    float4 o2 = make_float4(CLAMP1(a2.x + bv2), CLAMP1(a2.y + bv2),
                            CLAMP1(a2.z + bv2), CLAMP1(a2.w + bv2));
#undef CLAMP1

    float4* __restrict__ out4 = (float4*)out;
    const size_t obase = (size_t)b * COUT * (HW / 4);
    __stcs(&out4[obase + 0 * (HW / 4) + hw4], o0);
    __stcs(&out4[obase + 1 * (HW / 4) + hw4], o1);
    __stcs(&out4[obase + 2 * (HW / 4) + hw4], o2);
}

// ---------------------------------------------------------------------------
// Launch
//   d_in[0] = x        [B, CIN, H, W]  f32
//   d_in[1] = w        [B, WDIM]       f32
//   d_in[2] = weight   [COUT, CIN,1,1] f32
//   d_in[3] = bias     [COUT]          f32
//   d_in[4] = affine_w [CIN, WDIM]     f32
//   d_in[5] = affine_b [CIN]           f32
// ---------------------------------------------------------------------------
extern "C" void kernel_launch(void* const* d_in, const int* in_sizes, int n_in,
                              void* d_out, int out_size)
{
    const float* x        = (const float*)d_in[0];
    const float* w        = (const float*)d_in[1];
    const float* weight   = (const float*)d_in[2];
    const float* bias     = (const float*)d_in[3];
    const float* affine_w = (const float*)d_in[4];
    const float* affine_b = (const float*)d_in[5];
    float* out = (float*)d_out;

    dim3 sgrid(CIN / 8, B_DIM);
    styles_kernel<<<sgrid, 256>>>(w, weight, affine_w, affine_b);

    dim3 cgrid(HW / 4 / 256, B_DIM);
    torgb_kernel<<<cgrid, 256>>>(x, bias, out);
}